// round 16
// baseline (speedup 1.0000x reference)
#include <cuda_runtime.h>
#include <cuda_bf16.h>
#include <cstdint>

// SpectralInverse, SINGLE kernel:
//   out[p,o] = u_b[o] + sum_f cos(2pi*Y[p,f]) * G[f,o],  G = h.u_w^T/N
//   G computed once per launch by CTAs 0..255 (warp-per-word, 8 words/CTA = 2048),
//   published via g_G + atomic counter; all CTAs overlap staging with the wait.
//   Counters reset by last-exiting CTA -> every launch identical (graph-safe).
// Main loop: R10 structure (best measured): Y via fused k16 split-MMA, cos via MUFU,
//   two k16 main MMAs per kt. TPB=256, launch_bounds(256,4).

#define BATCH 4
#define NF 128
#define CIN 64
#define COUT 8
#define NGRID (48*48*48)
#define TPB 256
#define PTS_PER_CTA 256
#define CTAS_PER_BATCH (NGRID / PTS_PER_CTA)   // 432
#define NCTAS (BATCH * CTAS_PER_BATCH)         // 1728
#define TWO_PI_F 6.28318530717958647692f
#define WBSTRIDE 136
#define NGWORDS (BATCH * 64 * COUT)            // 2048

__device__ uint32_t g_G[NGWORDS];              // bf16x2 words [batch][f/2][o]
__device__ int g_done = 0;
__device__ int g_exit = 0;

__device__ __forceinline__ uint32_t pack_bf16x2(float lo, float hi) {
    uint32_t r;
    asm("cvt.rn.bf16x2.f32 %0, %1, %2;" : "=r"(r) : "f"(hi), "f"(lo));
    return r;  // r[15:0]=bf16(lo), r[31:16]=bf16(hi)
}
__device__ __forceinline__ float bf16rt(float x) {
    return __bfloat162float(__float2bfloat16(x));
}

__device__ __forceinline__ void mma16816(float* d,
                                          uint32_t a0, uint32_t a1, uint32_t a2, uint32_t a3,
                                          uint32_t b0, uint32_t b1) {
    asm volatile("mma.sync.aligned.m16n8k16.row.col.f32.bf16.bf16.f32 "
                 "{%0,%1,%2,%3}, {%4,%5,%6,%7}, {%8,%9}, {%0,%1,%2,%3};"
                 : "+f"(d[0]), "+f"(d[1]), "+f"(d[2]), "+f"(d[3])
                 : "r"(a0), "r"(a1), "r"(a2), "r"(a3), "r"(b0), "r"(b1));
}
__device__ __forceinline__ void mma16816_z(float* d,
                                            uint32_t a0, uint32_t a1, uint32_t a2, uint32_t a3,
                                            uint32_t b0, uint32_t b1) {
    asm volatile("mma.sync.aligned.m16n8k16.row.col.f32.bf16.bf16.f32 "
                 "{%0,%1,%2,%3}, {%4,%5,%6,%7}, {%8,%9}, {%10,%10,%10,%10};"
                 : "=f"(d[0]), "=f"(d[1]), "=f"(d[2]), "=f"(d[3])
                 : "r"(a0), "r"(a1), "r"(a2), "r"(a3), "r"(b0), "r"(b1), "f"(0.0f));
}

// Position A-fragment word for k-slots (2t,2t+1) of [x_h,y_h,z_h,1, x_m,y_m,z_m,1]
__device__ __forceinline__ uint32_t apos(float4 q, int t) {
    float xh = bf16rt(q.x), yh = bf16rt(q.y), zh = bf16rt(q.z);
    if (t == 0) return pack_bf16x2(xh, yh);
    if (t == 1) return pack_bf16x2(zh, 1.0f);
    if (t == 2) return pack_bf16x2(q.x - xh, q.y - yh);
    return pack_bf16x2(q.z - zh, 1.0f);
}

__global__ void __launch_bounds__(TPB, 4)
spectral_single_kernel(const float* __restrict__ h,
                       const float* __restrict__ y,
                       const float* __restrict__ y_w,
                       const float* __restrict__ y_b,
                       const float* __restrict__ u_w,
                       const float* __restrict__ u_b,
                       float* __restrict__ out)
{
    __shared__ float4   s_pts[PTS_PER_CTA];       // 4096 B
    __shared__ uint32_t s_wb[2 * 4 * WBSTRIDE];   // 4352 B (Y-MMA B frags: pass1 | pass2)
    __shared__ uint32_t s_G[64 * COUT];           // 2048 B
    __shared__ float    s_ub[COUT];

    const int tid  = threadIdx.x;
    const int warp = tid >> 5;
    const int lane = tid & 31;
    const int g = lane >> 2;
    const int t = lane & 3;
    const int bIdx = blockIdx.x / CTAS_PER_BATCH;
    const int blk  = blockIdx.x % CTAS_PER_BATCH;

    // ---- producer: CTAs 0..255, warp-per-word G = h.u_w^T/N ----
    if (blockIdx.x < NGWORDS / 8) {
        const int w  = blockIdx.x * 8 + warp;   // word 0..2047
        const int b  = w >> 9;
        const int fp = (w >> 3) & 63;
        const int o  = w & 7;
        const float2* h0 = (const float2*)(h + ((size_t)b * NF + 2 * fp) * CIN);
        const float2* h1 = (const float2*)(h + ((size_t)b * NF + 2 * fp + 1) * CIN);
        const float2* uw = (const float2*)(u_w + o * CIN);
        float2 u  = uw[lane];
        float2 a0 = h0[lane];
        float2 a1 = h1[lane];
        float g0 = fmaf(a0.x, u.x, a0.y * u.y);
        float g1 = fmaf(a1.x, u.x, a1.y * u.y);
        #pragma unroll
        for (int off = 16; off > 0; off >>= 1) {
            g0 += __shfl_xor_sync(0xFFFFFFFFu, g0, off);
            g1 += __shfl_xor_sync(0xFFFFFFFFu, g1, off);
        }
        if (lane == 0) {
            const float inv_n = 1.0f / (float)NGRID;
            g_G[w] = pack_bf16x2(g0 * inv_n, g1 * inv_n);
            __threadfence();
            atomicAdd(&g_done, 1);
        }
    }

    // ---- staging (overlaps producer latency): Y-MMA B fragments ----
    {
        const int f = tid & 127;
        const int sec = tid >> 7;
        float wx = TWO_PI_F * y_w[f * 3], wy = TWO_PI_F * y_w[f * 3 + 1];
        float wz = TWO_PI_F * y_w[f * 3 + 2], bb = TWO_PI_F * y_b[f];
        float wxh = bf16rt(wx), wyh = bf16rt(wy), wzh = bf16rt(wz), bh_ = bf16rt(bb);
        float wxm = wx - wxh, wym = wy - wyh, wzm = wz - wzh, bm_ = bb - bh_;
        #pragma unroll
        for (int ee = 0; ee < 4; ee++) {
            int e = sec * 4 + ee;
            int pass = e >> 2, j = e & 3;
            float lo, hi;
            if (pass == 0) {
                if (j == 0 || j == 2) { lo = wxh; hi = wyh; }
                else if (j == 1)      { lo = wzh; hi = bh_; }
                else                  { lo = wzh; hi = bm_; }
            } else {
                if (j == 0 || j == 2) { lo = wxm; hi = wym; }
                else                  { lo = wzm; hi = 0.0f; }
            }
            s_wb[pass * (4 * WBSTRIDE) + j * WBSTRIDE + f] = pack_bf16x2(lo, hi);
        }
    }
    // ---- staging: grid positions ----
    {
        const float* yg = y + ((size_t)bIdx * NGRID + (size_t)blk * PTS_PER_CTA) * 3;
        float* sp = (float*)s_pts;
        #pragma unroll
        for (int it = 0; it < 4; it++) {
            int j = tid + it * TPB;
            int pt = j >> 2, c = j & 3;
            sp[j] = (c < 3) ? yg[pt * 3 + c] : 0.0f;
        }
    }
    if (tid < COUT) s_ub[tid] = u_b[tid];

    // ---- wait for all G words, then load them ----
    if (tid == 0) {
        while (atomicAdd(&g_done, 0) < NGWORDS) __nanosleep(64);
    }
    __syncthreads();
    __threadfence();
    #pragma unroll
    for (int it = 0; it < 2; it++)
        s_G[tid + it * TPB] = g_G[bIdx * (64 * COUT) + tid + it * TPB];
    __syncthreads();

    // ---- main loop: per-warp M=32 rows x K=128 x N=8 (R10 structure) ----
    const int base = warp * 32;

    const uint32_t aP00 = apos(s_pts[base + g],      t);
    const uint32_t aP01 = apos(s_pts[base + g + 8],  t);
    const uint32_t aP10 = apos(s_pts[base + g + 16], t);
    const uint32_t aP11 = apos(s_pts[base + g + 24], t);

    const float ub0 = s_ub[2 * t], ub1 = s_ub[2 * t + 1];
    float acc0[4] = {ub0, ub1, ub0, ub1};
    float acc1[4] = {ub0, ub1, ub0, ub1};

    const uint32_t* wb0 = s_wb + t * WBSTRIDE + g;

    #pragma unroll
    for (int kt = 0; kt < 8; kt++) {
        uint32_t a0, a1, a2, a3, a4, a5, a6, a7;
        #pragma unroll
        for (int nt2 = 0; nt2 < 2; nt2++) {
            const uint32_t col = kt * 16 + nt2 * 8;
            uint32_t c1 = wb0[col];                    // pass1 (k-rows 0-7)
            uint32_t c2 = wb0[4 * WBSTRIDE + col];     // pass2 (k-rows 8-15)
            float d0[4], d1[4];
            mma16816_z(d0, aP00, aP01, aP00, aP01, c1, c2);
            mma16816_z(d1, aP10, aP11, aP10, aP11, c1, c2);
            uint32_t f0 = pack_bf16x2(__cosf(d0[0]), __cosf(d0[1]));
            uint32_t f1 = pack_bf16x2(__cosf(d0[2]), __cosf(d0[3]));
            uint32_t f2 = pack_bf16x2(__cosf(d1[0]), __cosf(d1[1]));
            uint32_t f3 = pack_bf16x2(__cosf(d1[2]), __cosf(d1[3]));
            if (nt2 == 0) { a0 = f0; a1 = f1; a4 = f2; a5 = f3; }
            else          { a2 = f0; a3 = f1; a6 = f2; a7 = f3; }
        }
        uint32_t b0 = s_G[(kt * 8 + t) * 8 + g];
        uint32_t b1 = s_G[(kt * 8 + t + 4) * 8 + g];
        mma16816(acc0, a0, a1, a2, a3, b0, b1);
        mma16816(acc1, a4, a5, a6, a7, b0, b1);
    }

    const size_t pt = (size_t)bIdx * NGRID + (size_t)blk * PTS_PER_CTA + base + g;
    *(float2*)(out + (pt +  0) * COUT + 2 * t) = make_float2(acc0[0], acc0[1]);
    *(float2*)(out + (pt +  8) * COUT + 2 * t) = make_float2(acc0[2], acc0[3]);
    *(float2*)(out + (pt + 16) * COUT + 2 * t) = make_float2(acc1[0], acc1[1]);
    *(float2*)(out + (pt + 24) * COUT + 2 * t) = make_float2(acc1[2], acc1[3]);

    // ---- exit protocol: last CTA resets counters so every launch is identical ----
    __syncthreads();
    if (tid == 0) {
        int old = atomicAdd(&g_exit, 1);
        if (old == NCTAS - 1) {
            g_done = 0;
            g_exit = 0;
            __threadfence();
        }
    }
}

extern "C" void kernel_launch(void* const* d_in, const int* in_sizes, int n_in,
                              void* d_out, int out_size) {
    const float* h   = (const float*)d_in[0];
    const float* y   = (const float*)d_in[1];
    const float* y_w = (const float*)d_in[2];
    const float* y_b = (const float*)d_in[3];
    const float* u_w = (const float*)d_in[4];
    const float* u_b = (const float*)d_in[5];
    float* out = (float*)d_out;

    dim3 grid(NCTAS);   // 1728 CTAs, single launch
    spectral_single_kernel<<<grid, TPB>>>(h, y, y_w, y_b, u_w, u_b, out);
}

// round 17
// speedup vs baseline: 1.1758x; 1.1758x over previous
#include <cuda_runtime.h>
#include <cuda_bf16.h>
#include <cstdint>

// SpectralInverse, linearized tail + tensorized Y + tf32 main contraction:
//   out[p,o] = u_b[o] + sum_f cos(2pi*Y[p,f]) * G[f,o],  G = h.u_w^T/N (precomputed fp32)
//   Y via m16n8k16 bf16 split-MMA (f->n-slot PERMUTED so D-frag == tf32 A-frag layout),
//   cos (MUFU, fp32) feeds mma.m16n8k8.tf32 DIRECTLY (no bf16 packing stage).

#define BATCH 4
#define NF 128
#define CIN 64
#define COUT 8
#define NGRID (48*48*48)
#define TPB 256
#define PTS_PER_CTA 256
#define CTAS_PER_BATCH (NGRID / PTS_PER_CTA)   // 432
#define TWO_PI_F 6.28318530717958647692f
#define WBSTRIDE 136   // uint2 per j-row

__device__ float g_Gf[BATCH * NF * COUT];      // fp32 G [batch][f][o]

__device__ __forceinline__ uint32_t pack_bf16x2(float lo, float hi) {
    uint32_t r;
    asm("cvt.rn.bf16x2.f32 %0, %1, %2;" : "=r"(r) : "f"(hi), "f"(lo));
    return r;
}
__device__ __forceinline__ float bf16rt(float x) {
    return __bfloat162float(__float2bfloat16(x));
}

// Y: m16n8k16 bf16, D = A*B (fresh accumulator)
__device__ __forceinline__ void mma16816_z(float* d,
                                            uint32_t a0, uint32_t a1, uint32_t a2, uint32_t a3,
                                            uint32_t b0, uint32_t b1) {
    asm volatile("mma.sync.aligned.m16n8k16.row.col.f32.bf16.bf16.f32 "
                 "{%0,%1,%2,%3}, {%4,%5,%6,%7}, {%8,%9}, {%10,%10,%10,%10};"
                 : "=f"(d[0]), "=f"(d[1]), "=f"(d[2]), "=f"(d[3])
                 : "r"(a0), "r"(a1), "r"(a2), "r"(a3), "r"(b0), "r"(b1), "f"(0.0f));
}
// Main: m16n8k8 tf32, D += A*B  (A,B are fp32 regs; HW truncates to tf32)
__device__ __forceinline__ void mma_tf32(float* d,
                                          float a0, float a1, float a2, float a3,
                                          float b0, float b1) {
    asm volatile("mma.sync.aligned.m16n8k8.row.col.f32.tf32.tf32.f32 "
                 "{%0,%1,%2,%3}, {%4,%5,%6,%7}, {%8,%9}, {%0,%1,%2,%3};"
                 : "+f"(d[0]), "+f"(d[1]), "+f"(d[2]), "+f"(d[3])
                 : "f"(a0), "f"(a1), "f"(a2), "f"(a3), "f"(b0), "f"(b1));
}

// Position A-fragment word for k-slots (2t,2t+1) of [x_h,y_h,z_h,1, x_m,y_m,z_m,1]
__device__ __forceinline__ uint32_t apos(float4 q, int t) {
    float xh = bf16rt(q.x), yh = bf16rt(q.y), zh = bf16rt(q.z);
    if (t == 0) return pack_bf16x2(xh, yh);
    if (t == 1) return pack_bf16x2(zh, 1.0f);
    if (t == 2) return pack_bf16x2(q.x - xh, q.y - yh);
    return pack_bf16x2(q.z - zh, 1.0f);
}

// ---------------- kernel 1: G = h . u_w^T / N (fp32) — one warp per f-pair/o ----------------
__global__ void __launch_bounds__(256)
precompute_G_kernel(const float* __restrict__ h, const float* __restrict__ u_w)
{
    const int w    = blockIdx.x * 8 + (threadIdx.x >> 5);   // 0..2047
    const int lane = threadIdx.x & 31;
    const int b  = w >> 9;
    const int fp = (w >> 3) & 63;
    const int o  = w & 7;

    const float2* h0 = (const float2*)(h + ((size_t)b * NF + 2 * fp) * CIN);
    const float2* h1 = (const float2*)(h + ((size_t)b * NF + 2 * fp + 1) * CIN);
    const float2* uw = (const float2*)(u_w + o * CIN);

    float2 u  = uw[lane];
    float2 a0 = h0[lane];
    float2 a1 = h1[lane];
    float g0 = fmaf(a0.x, u.x, a0.y * u.y);
    float g1 = fmaf(a1.x, u.x, a1.y * u.y);
    #pragma unroll
    for (int off = 16; off > 0; off >>= 1) {
        g0 += __shfl_xor_sync(0xFFFFFFFFu, g0, off);
        g1 += __shfl_xor_sync(0xFFFFFFFFu, g1, off);
    }
    if (lane == 0) {
        const float inv_n = 1.0f / (float)NGRID;
        g_Gf[b * (NF * COUT) + (2 * fp) * COUT + o]     = g0 * inv_n;
        g_Gf[b * (NF * COUT) + (2 * fp + 1) * COUT + o] = g1 * inv_n;
    }
}

// ---------------- kernel 2: main ----------------
__global__ void __launch_bounds__(TPB, 4)
spectral_tf32_kernel(const float* __restrict__ y,
                     const float* __restrict__ y_w,
                     const float* __restrict__ y_b,
                     const float* __restrict__ u_b,
                     float* __restrict__ out)
{
    __shared__ float4 s_pts[PTS_PER_CTA];      // 4096 B
    __shared__ uint2  s_wb[4 * WBSTRIDE];      // 4352 B (.x=pass1, .y=pass2), f PERMUTED
    __shared__ float2 s_Gt[16 * 4 * COUT];     // 4096 B (.x=G[f=8grp+t][o], .y=G[f=8grp+t+4][o])
    __shared__ float  s_ub[COUT];

    const int tid  = threadIdx.x;
    const int warp = tid >> 5;
    const int lane = tid & 31;
    const int g = lane >> 2;
    const int t = lane & 3;
    const int bIdx = blockIdx.x / CTAS_PER_BATCH;
    const int blk  = blockIdx.x % CTAS_PER_BATCH;

    // ---- staging: Y-MMA B fragments, f -> n-slot permuted ----
    // n-slot 2u holds f = base+u; n-slot 2u+1 holds f = base+u+4  (so D-frag == tf32 A-frag)
    {
        const int f = tid & 127;
        const int sec = tid >> 7;                 // 0..1 -> j = 2*sec, 2*sec+1
        const int r = f & 7;
        const int slot = (f & ~7) + ((r < 4) ? (2 * r) : (2 * (r - 4) + 1));
        float wx = TWO_PI_F * y_w[f * 3], wy = TWO_PI_F * y_w[f * 3 + 1];
        float wz = TWO_PI_F * y_w[f * 3 + 2], bb = TWO_PI_F * y_b[f];
        float wxh = bf16rt(wx), wyh = bf16rt(wy), wzh = bf16rt(wz), bh_ = bf16rt(bb);
        #pragma unroll
        for (int jj = 0; jj < 2; jj++) {
            int j = sec * 2 + jj;
            float lo1, hi1, lo2, hi2;
            if (j == 0 || j == 2) { lo1 = wxh; hi1 = wyh; lo2 = wx - wxh; hi2 = wy - wyh; }
            else if (j == 1)      { lo1 = wzh; hi1 = bh_;      lo2 = wz - wzh; hi2 = 0.0f; }
            else                  { lo1 = wzh; hi1 = bb - bh_; lo2 = wz - wzh; hi2 = 0.0f; }
            s_wb[j * WBSTRIDE + slot] = make_uint2(pack_bf16x2(lo1, hi1), pack_bf16x2(lo2, hi2));
        }
    }
    // ---- staging: grid positions ----
    {
        const float* yg = y + ((size_t)bIdx * NGRID + (size_t)blk * PTS_PER_CTA) * 3;
        float* sp = (float*)s_pts;
        #pragma unroll
        for (int it = 0; it < 4; it++) {
            int j = tid + it * TPB;
            int pt = j >> 2, c = j & 3;
            sp[j] = (c < 3) ? yg[pt * 3 + c] : 0.0f;
        }
    }
    // ---- staging: G (fp32) into tf32-B layout ----
    #pragma unroll
    for (int it = 0; it < 4; it++) {
        int i = tid + it * TPB;                   // 0..1023
        int f = i >> 3, o = i & 7;
        float v = g_Gf[bIdx * (NF * COUT) + i];
        int grp = f >> 3, r = f & 7;
        if (r < 4) s_Gt[(grp * 4 + r) * 8 + o].x = v;
        else       s_Gt[(grp * 4 + r - 4) * 8 + o].y = v;
    }
    if (tid < COUT) s_ub[tid] = u_b[tid];
    __syncthreads();

    // ---- per-warp: M=32 rows x K=128 x N=8 ----
    const int base = warp * 32;

    const uint32_t aP00 = apos(s_pts[base + g],      t);
    const uint32_t aP01 = apos(s_pts[base + g + 8],  t);
    const uint32_t aP10 = apos(s_pts[base + g + 16], t);
    const uint32_t aP11 = apos(s_pts[base + g + 24], t);

    const float ub0 = s_ub[2 * t], ub1 = s_ub[2 * t + 1];
    float acc0[4] = {ub0, ub1, ub0, ub1};
    float acc1[4] = {ub0, ub1, ub0, ub1};

    const uint2*  wb0 = s_wb + t * WBSTRIDE + g;
    const float2* sg0 = s_Gt + t * 8 + g;

    #pragma unroll
    for (int kt = 0; kt < 8; kt++) {
        #pragma unroll
        for (int nt2 = 0; nt2 < 2; nt2++) {
            const int grp = kt * 2 + nt2;
            const uint2  c  = wb0[grp * 8];       // .x=pass1, .y=pass2
            const float2 bg = sg0[grp * 32];      // .x=G[f=t], .y=G[f=t+4]
            float d0[4], d1[4];
            mma16816_z(d0, aP00, aP01, aP00, aP01, c.x, c.y);
            mma16816_z(d1, aP10, aP11, aP10, aP11, c.x, c.y);
            // cos results ARE the tf32 A fragment (a-order: d0, d2, d1, d3)
            mma_tf32(acc0, __cosf(d0[0]), __cosf(d0[2]), __cosf(d0[1]), __cosf(d0[3]),
                     bg.x, bg.y);
            mma_tf32(acc1, __cosf(d1[0]), __cosf(d1[2]), __cosf(d1[1]), __cosf(d1[3]),
                     bg.x, bg.y);
        }
    }

    const size_t pt = (size_t)bIdx * NGRID + (size_t)blk * PTS_PER_CTA + base + g;
    *(float2*)(out + (pt +  0) * COUT + 2 * t) = make_float2(acc0[0], acc0[1]);
    *(float2*)(out + (pt +  8) * COUT + 2 * t) = make_float2(acc0[2], acc0[3]);
    *(float2*)(out + (pt + 16) * COUT + 2 * t) = make_float2(acc1[0], acc1[1]);
    *(float2*)(out + (pt + 24) * COUT + 2 * t) = make_float2(acc1[2], acc1[3]);
}

extern "C" void kernel_launch(void* const* d_in, const int* in_sizes, int n_in,
                              void* d_out, int out_size) {
    const float* h   = (const float*)d_in[0];
    const float* y   = (const float*)d_in[1];
    const float* y_w = (const float*)d_in[2];
    const float* y_b = (const float*)d_in[3];
    const float* u_w = (const float*)d_in[4];
    const float* u_b = (const float*)d_in[5];
    float* out = (float*)d_out;

    precompute_G_kernel<<<256, 256>>>(h, u_w);
    dim3 grid(BATCH * CTAS_PER_BATCH);   // 1728 CTAs
    spectral_tf32_kernel<<<grid, TPB>>>(y, y_w, y_b, u_b, out);
}